// round 15
// baseline (speedup 1.0000x reference)
#include <cuda_runtime.h>
#include <cuda_fp16.h>

#define NNODE 20000
#define NU    512
#define NE    81920
#define NBAT  8
#define NC    64
#define SEG   (NE / NU)        // 160 expected incidences per hyperedge
#define SCAN_BS 256
#define NSB   ((NNODE + SCAN_BS - 1) / SCAN_BS)   // 79
#define NPART 4                // gather blocks per hyperedge
#define NSLOT 8                // partial slots per u (agg gather: 4 parts x 2 js)
#define NSLOT1 16              // partial slots per u (out1 gather: 4 parts x 4 js)

// ---------------- device scratch ----------------
__device__ int   g_idx64;
__device__ int   g_uniform;
__device__ int   g_deg[NNODE];
__device__ int   g_rowstart[NNODE + 1];
__device__ int   g_cursor[NNODE];
__device__ int   g_bsum[NSB];
__device__ int   g_boff[NSB];
__device__ unsigned g_scan_ctr;
__device__ int   g_scan_flag;
__device__ int   g_perm[NE];
__device__ int   g_uperm[NE];
__device__ float g_si[NNODE * NBAT];
__device__ float g_sj[NU * NBAT];
__device__ float g_qt[NBAT * NC * NU];        // [b][c][u]
__device__ float g_kt[NBAT * NC * NU];        // [b][c][u]
__device__ float g_vj[NBAT * NU];
__device__ float g_wv[NC];
__device__ float g_cv;
__device__ float g_bn[NU];
__device__ float g_alpha_e[NE * NBAT];        // normalized alpha, original order
__device__ float g_alpha_p[NE * NBAT];        // normalized alpha, node-CSR order
__device__ uint4 g_xh[NBAT * NNODE * 8];      // fp16 x copy: [b][n][8x uint4]
__device__ uint4 g_out1h[NU * NBAT * 8];      // fp16 out1: [u][b][8x uint4]
__device__ float4 g_part[NU * NSLOT1 * 128];  // partial slots (16 MB)

struct H8 { __half2 a, b, c, d; };

__device__ __forceinline__ int nodeAt(const int* hi, int e, int is64) {
    return is64 ? hi[2 * e] : hi[e];
}
__device__ __forceinline__ int edgeAt(const int* hi, int e, int is64) {
    return is64 ? hi[2 * (NE + e)] : hi[NE + e];
}
__device__ __forceinline__ int edgeLB(const int* hi, int target, int is64) {
    int lo = 0, hi_ = NE;
    while (lo < hi_) {
        int mid = (lo + hi_) >> 1;
        if (edgeAt(hi, mid, is64) < target) lo = mid + 1; else hi_ = mid;
    }
    return lo;
}

// ---------------- init: zero deg + detect dtype + uniformity + weff ----------------
__global__ void k_init(const int* __restrict__ hi, const float* __restrict__ att,
                       const float* __restrict__ Wv, const float* __restrict__ bv) {
    int blk = blockIdx.x;
    if (blk < NSB) {
        int i = blk * 256 + threadIdx.x;
        if (i < NNODE) g_deg[i] = 0;
        return;
    }
    __shared__ int s_is64;
    __shared__ int s_ok;
    int t = threadIdx.x;
    if (t == 0) {
        int odd_or = 0;
        for (int i = 0; i < 64; i++) odd_or |= hi[2 * i + 1];
        int is64 = (odd_or == 0) ? 1 : 0;
        g_idx64 = is64;
        s_is64 = is64;
        s_ok = 1;
        g_scan_ctr = 0;
        g_scan_flag = 0;
    }
    if (t < NC) {
        float w = 0.f;
        for (int c = 0; c < NC; c++) w += Wv[c * NC + t] * att[NC + c];
        g_wv[t] = w;
        if (t == 0) {
            float cv = 0.f;
            for (int c = 0; c < NC; c++) cv += bv[c] * att[NC + c];
            g_cv = cv;
        }
    }
    __syncthreads();
    int is64 = s_is64;
    int ok = 1;
    for (int u = t; u < NU; u += 256) {
        if (edgeAt(hi, u * SEG, is64) != u) ok = 0;
        if (edgeAt(hi, u * SEG + SEG - 1, is64) != u) ok = 0;
    }
    if (!ok) atomicAnd(&s_ok, 0);
    __syncthreads();
    if (t == 0) g_uniform = s_ok;
}

__global__ void k_hist(const int* __restrict__ hi) {
    int i = blockIdx.x * blockDim.x + threadIdx.x;
    if (i >= NE) return;
    atomicAdd(&g_deg[nodeAt(hi, i, g_idx64)], 1);
}

// ---------------- single-kernel scan ----------------
__global__ void k_scan() {
    __shared__ int wsum[8];
    __shared__ int isLast;
    int tid = threadIdx.x, lane = tid & 31, w = tid >> 5;
    int i = blockIdx.x * SCAN_BS + tid;
    int v = (i < NNODE) ? g_deg[i] : 0;
    int xv = v;
    #pragma unroll
    for (int o = 1; o < 32; o <<= 1) {
        int y = __shfl_up_sync(0xffffffffu, xv, o);
        if (lane >= o) xv += y;
    }
    if (lane == 31) wsum[w] = xv;
    __syncthreads();
    if (w == 0) {
        int t = (lane < 8) ? wsum[lane] : 0;
        #pragma unroll
        for (int o = 1; o < 8; o <<= 1) {
            int y = __shfl_up_sync(0xffffffffu, t, o);
            if (lane >= o) t += y;
        }
        if (lane < 8) wsum[lane] = t;
    }
    __syncthreads();
    int woff = (w == 0) ? 0 : wsum[w - 1];
    int local_excl = woff + xv - v;
    if (tid == 0) g_bsum[blockIdx.x] = wsum[7];
    __threadfence();
    if (tid == 0) {
        unsigned d = atomicAdd(&g_scan_ctr, 1u);
        isLast = (d == NSB - 1) ? 1 : 0;
    }
    __syncthreads();
    if (isLast) {
        int v2 = (tid < NSB) ? g_bsum[tid] : 0;
        int xv2 = v2;
        #pragma unroll
        for (int o = 1; o < 32; o <<= 1) {
            int y = __shfl_up_sync(0xffffffffu, xv2, o);
            if (lane >= o) xv2 += y;
        }
        __syncthreads();
        if (lane == 31) wsum[w] = xv2;
        __syncthreads();
        if (w == 0) {
            int t = (lane < 8) ? wsum[lane] : 0;
            #pragma unroll
            for (int o = 1; o < 8; o <<= 1) {
                int y = __shfl_up_sync(0xffffffffu, t, o);
                if (lane >= o) t += y;
            }
            if (lane < 8) wsum[lane] = t;
        }
        __syncthreads();
        int woff2 = (w == 0) ? 0 : wsum[w - 1];
        if (tid < NSB) g_boff[tid] = woff2 + xv2 - v2;
        __threadfence();
        __syncthreads();
        if (tid == 0) atomicExch(&g_scan_flag, 1);
    } else {
        if (tid == 0) {
            while (atomicAdd(&g_scan_flag, 0) == 0) __nanosleep(40);
        }
        __syncthreads();
    }
    int boff = __ldcg(&g_boff[blockIdx.x]);
    if (i < NNODE) {
        int r = local_excl + boff;
        g_rowstart[i] = r;
        g_cursor[i] = r;
    }
    if (i == 0) g_rowstart[NNODE] = NE;
}

// ---------------- fused scatter + s_i + x->fp16 ----------------
#define SCAT_BLOCKS (NE / 256)                          // 320
#define SI_BLOCKS   ((NNODE * NBAT + 255) / 256)        // 625
__global__ void k_scatsi(const int* __restrict__ hi, const float* __restrict__ x,
                         const float* __restrict__ att) {
    int blk = blockIdx.x;
    if (blk < SCAT_BLOCKS) {
        int e = blk * 256 + threadIdx.x;
        int is64 = g_idx64;
        int n = nodeAt(hi, e, is64);
        int pos = atomicAdd(&g_cursor[n], 1);
        g_perm[pos] = e;
        g_uperm[pos] = edgeAt(hi, e, is64);
        return;
    }
    int idx = (blk - SCAT_BLOCKS) * 256 + threadIdx.x;
    if (idx >= NNODE * NBAT) return;
    int b = idx / NNODE;
    int n = idx - b * NNODE;
    const float4* x4 = (const float4*)x + (size_t)idx * 16;
    const float4* a4 = (const float4*)att;
    float v = 0.f;
    #pragma unroll
    for (int i = 0; i < 16; i += 2) {
        float4 xa = x4[i], xb = x4[i + 1];
        float4 aa = a4[i], ab = a4[i + 1];
        v += xa.x * aa.x + xa.y * aa.y + xa.z * aa.z + xa.w * aa.w;
        v += xb.x * ab.x + xb.y * ab.y + xb.z * ab.z + xb.w * ab.w;
        H8 h;
        h.a = __floats2half2_rn(xa.x, xa.y);
        h.b = __floats2half2_rn(xa.z, xa.w);
        h.c = __floats2half2_rn(xb.x, xb.y);
        h.d = __floats2half2_rn(xb.z, xb.w);
        g_xh[(size_t)idx * 8 + (i >> 1)] = *(uint4*)&h;
    }
    g_si[n * NBAT + b] = v;
}

// ---------------- agg gather: 4 blocks per u, fp32 x (attention path) ----------------
__global__ void __launch_bounds__(256, 8) k_gather(const float* __restrict__ x,
                                                   const int* __restrict__ hi) {
    int blk = blockIdx.x;                 // NU*4 = 2048
    int u = blk >> 2, part = blk & 3;
    int is64 = g_idx64;
    __shared__ int sb[2];
    if (g_uniform) {
        if (threadIdx.x < 2) sb[threadIdx.x] = (u + threadIdx.x) * SEG;
    } else {
        if (threadIdx.x < 2) sb[threadIdx.x] = edgeLB(hi, u + threadIdx.x, is64);
    }
    __syncthreads();
    int start = sb[0], end = sb[1];
    int len = end - start;
    int chunk = (len + NPART - 1) / NPART;
    int lo = start + part * chunk;
    int hi_ = min(lo + chunk, end);

    int js = threadIdx.x >> 7;            // 2 j-slots
    int b  = (threadIdx.x >> 4) & 7;
    int c4 = threadIdx.x & 15;
    const float4* x4 = (const float4*)x;
    float4 acc = make_float4(0.f, 0.f, 0.f, 0.f);
    #pragma unroll 4
    for (int j = lo + js; j < hi_; j += 2) {
        int n = nodeAt(hi, j, is64);
        float4 xv = x4[((size_t)b * NNODE + n) * 16 + c4];
        acc.x += xv.x; acc.y += xv.y; acc.z += xv.z; acc.w += xv.w;
    }
    g_part[(u * NSLOT + part * 2 + js) * 128 + b * 16 + c4] = acc;
}

// ---------------- project: reduce partials -> agg ; q,k,vj ----------------
__global__ void __launch_bounds__(256, 4) k_project(
        const int* __restrict__ hi,
        const float* __restrict__ Wq, const float* __restrict__ bq,
        const float* __restrict__ Wk, const float* __restrict__ bk) {
    __shared__ float wq_s[64 * 65];
    __shared__ float wk_s[64 * 65];
    __shared__ float agg_s[8][65];
    __shared__ float wv_s[64];
    int u = blockIdx.x;
    int tid = threadIdx.x;

    for (int i = tid; i < 4096; i += 256) {
        int c = i >> 6, k = i & 63;
        wq_s[c * 65 + k] = Wq[i];
        wk_s[c * 65 + k] = Wk[i];
    }
    if (tid < 64) wv_s[tid] = g_wv[tid];
    if (tid == 0) {
        int len = g_uniform ? SEG : (edgeLB(hi, u + 1, g_idx64) - edgeLB(hi, u, g_idx64));
        g_bn[u] = (len > 0) ? 1.0f / (float)len : 0.0f;
    }
    if (tid < 128) {
        float4 r = make_float4(0.f, 0.f, 0.f, 0.f);
        #pragma unroll
        for (int s = 0; s < NSLOT; s++) {
            float4 t = g_part[(u * NSLOT + s) * 128 + tid];
            r.x += t.x; r.y += t.y; r.z += t.z; r.w += t.w;
        }
        int bb = tid >> 4, cc = (tid & 15) * 4;
        agg_s[bb][cc + 0] = r.x;
        agg_s[bb][cc + 1] = r.y;
        agg_s[bb][cc + 2] = r.z;
        agg_s[bb][cc + 3] = r.w;
    }
    __syncthreads();

    #pragma unroll
    for (int p = 0; p < 2; p++) {
        int pp = tid + p * 256;
        int c = pp & 63, b2 = pp >> 6;
        float qa = bq[c], ka = bk[c];
        #pragma unroll 8
        for (int k = 0; k < 64; k++) {
            float a = agg_s[b2][k];
            qa += a * wq_s[c * 65 + k];
            ka += a * wk_s[c * 65 + k];
        }
        g_qt[(b2 * 64 + c) * NU + u] = qa;
        g_kt[(b2 * 64 + c) * NU + u] = ka;
    }

    int w = tid >> 5, lane = tid & 31;
    float v = agg_s[w][lane] * wv_s[lane] + agg_s[w][lane + 32] * wv_s[lane + 32];
    #pragma unroll
    for (int o = 16; o; o >>= 1) v += __shfl_down_sync(0xffffffffu, v, o);
    if (lane == 0) g_vj[w * NU + u] = v + g_cv;
}

// ---------------- masked attention + register softmax -> s_j ----------------
__global__ void __launch_bounds__(256, 1) k_attn(const float* __restrict__ adj) {
    extern __shared__ float sm[];
    float* k_s  = sm;
    float* q_s  = k_s + 64 * 512;
    float* vj_s = q_s + 64 * 32;
    __shared__ float redm[8][8];
    __shared__ float reds[8][8];
    __shared__ float redd[8][8];

    int b  = blockIdx.y;
    int u0 = blockIdx.x * 32;
    int tid = threadIdx.x;

    const float4* ksrc = (const float4*)(g_kt) + (size_t)b * (64 * NU / 4);
    float4* kdst = (float4*)k_s;
    for (int i = tid; i < 64 * NU / 4; i += 256) kdst[i] = ksrc[i];
    for (int i = tid; i < 64 * 32; i += 256) {
        int c = i >> 5, u = i & 31;
        q_s[c * 32 + u] = g_qt[(b * 64 + c) * NU + u0 + u];
    }
    for (int i = tid; i < 512; i += 256) vj_s[i] = g_vj[b * NU + i];
    __syncthreads();

    int g  = tid >> 6;
    int ug = g * 8;
    int vg = (tid & 63) * 8;
    float acc[8][8] = {};
    const float4* k4 = (const float4*)k_s;
    const float4* q4 = (const float4*)q_s;
    int kv_i = vg >> 2, qu_i = ug >> 2;
    #pragma unroll 4
    for (int kk = 0; kk < 64; kk++) {
        float4 kv0 = k4[kk * 128 + kv_i];
        float4 kv1 = k4[kk * 128 + kv_i + 1];
        float4 qv0 = q4[kk * 8 + qu_i];
        float4 qv1 = q4[kk * 8 + qu_i + 1];
        float qa[8] = {qv0.x, qv0.y, qv0.z, qv0.w, qv1.x, qv1.y, qv1.z, qv1.w};
        float kb[8] = {kv0.x, kv0.y, kv0.z, kv0.w, kv1.x, kv1.y, kv1.z, kv1.w};
        #pragma unroll
        for (int i = 0; i < 8; i++)
            #pragma unroll
            for (int j = 0; j < 8; j++)
                acc[i][j] += qa[i] * kb[j];
    }
    float rm[8];
    #pragma unroll
    for (int i = 0; i < 8; i++) {
        int u = ug + i;
        const float4* arow = (const float4*)(adj + (size_t)(u0 + u) * NU + vg);
        float4 a0 = arow[0], a1 = arow[1];
        acc[i][0] = acc[i][0] * 0.125f - (1.f - a0.x) * 500.f;
        acc[i][1] = acc[i][1] * 0.125f - (1.f - a0.y) * 500.f;
        acc[i][2] = acc[i][2] * 0.125f - (1.f - a0.z) * 500.f;
        acc[i][3] = acc[i][3] * 0.125f - (1.f - a0.w) * 500.f;
        acc[i][4] = acc[i][4] * 0.125f - (1.f - a1.x) * 500.f;
        acc[i][5] = acc[i][5] * 0.125f - (1.f - a1.y) * 500.f;
        acc[i][6] = acc[i][6] * 0.125f - (1.f - a1.z) * 500.f;
        acc[i][7] = acc[i][7] * 0.125f - (1.f - a1.w) * 500.f;
        float m = acc[i][0];
        #pragma unroll
        for (int j = 1; j < 8; j++) m = fmaxf(m, acc[i][j]);
        rm[i] = m;
    }
    int w = tid >> 5, lane = tid & 31;
    #pragma unroll
    for (int i = 0; i < 8; i++) {
        float m = rm[i];
        #pragma unroll
        for (int o = 16; o; o >>= 1) m = fmaxf(m, __shfl_xor_sync(0xffffffffu, m, o));
        if (lane == 0) redm[w][i] = m;
    }
    __syncthreads();
    #pragma unroll
    for (int i = 0; i < 8; i++) rm[i] = fmaxf(redm[g * 2][i], redm[g * 2 + 1][i]);

    float vjv[8];
    {
        const float4* v4 = (const float4*)(vj_s + vg);
        float4 v0 = v4[0], v1 = v4[1];
        vjv[0] = v0.x; vjv[1] = v0.y; vjv[2] = v0.z; vjv[3] = v0.w;
        vjv[4] = v1.x; vjv[5] = v1.y; vjv[6] = v1.z; vjv[7] = v1.w;
    }
    #pragma unroll
    for (int i = 0; i < 8; i++) {
        float s = 0.f, d = 0.f;
        #pragma unroll
        for (int j = 0; j < 8; j++) {
            float e = __expf(acc[i][j] - rm[i]);
            s += e;
            d += e * vjv[j];
        }
        #pragma unroll
        for (int o = 16; o; o >>= 1) {
            s += __shfl_xor_sync(0xffffffffu, s, o);
            d += __shfl_xor_sync(0xffffffffu, d, o);
        }
        if (lane == 0) { reds[w][i] = s; redd[w][i] = d; }
    }
    __syncthreads();
    if ((tid & 63) < 8) {
        int i = tid & 63;
        float s = reds[g * 2][i] + reds[g * 2 + 1][i];
        float d = redd[g * 2][i] + redd[g * 2 + 1][i];
        g_sj[(u0 + ug + i) * NBAT + b] = d / s;
    }
}

// ---------------- 2-pass node softmax (no max pass; |a| is O(1)) ----------------
__global__ void k_nodealpha() {
    int idx = blockIdx.x * blockDim.x + threadIdx.x;
    if (idx >= NNODE * NBAT) return;
    int n = idx >> 3, b = idx & 7;
    int s = g_rowstart[n], e2 = g_rowstart[n + 1];
    if (s == e2) return;
    float si = g_si[n * NBAT + b];
    float sum = 0.f;
    for (int j = s; j < e2; j++) {
        int u = g_uperm[j];
        float a = si + g_sj[u * NBAT + b];
        a = (a > 0.f) ? a : 0.2f * a;
        float ex = __expf(a);
        g_alpha_p[j * NBAT + b] = ex;
        sum += ex;
    }
    float inv = 1.0f / (sum + 1e-16f);
    for (int j = s; j < e2; j++) {
        float v = g_alpha_p[j * NBAT + b] * inv;
        g_alpha_p[j * NBAT + b] = v;
        g_alpha_e[g_perm[j] * NBAT + b] = v;
    }
}

// ---------------- out1 gather: fp16 x, 4 blocks per u, 4 j-slots ----------------
__global__ void __launch_bounds__(256, 6) k_gather1(const int* __restrict__ hi) {
    int blk = blockIdx.x;                 // NU*4
    int u = blk >> 2, part = blk & 3;
    int is64 = g_idx64;
    __shared__ int sb[2];
    if (g_uniform) {
        if (threadIdx.x < 2) sb[threadIdx.x] = (u + threadIdx.x) * SEG;
    } else {
        if (threadIdx.x < 2) sb[threadIdx.x] = edgeLB(hi, u + threadIdx.x, is64);
    }
    __syncthreads();
    int start = sb[0], end = sb[1];
    int len = end - start;
    int chunk = (len + NPART - 1) / NPART;
    int lo = start + part * chunk;
    int hi_ = min(lo + chunk, end);

    int js = threadIdx.x >> 6;            // 4 j-slots
    int b  = (threadIdx.x >> 3) & 7;
    int c8 = threadIdx.x & 7;             // channel-group of 8
    float acc[8] = {};
    #pragma unroll 2
    for (int j = lo + js; j < hi_; j += 4) {
        int n = nodeAt(hi, j, is64);
        float a = g_alpha_e[j * NBAT + b];
        uint4 hv = g_xh[((size_t)b * NNODE + n) * 8 + c8];
        __half2* hp = (__half2*)&hv;
        #pragma unroll
        for (int q = 0; q < 4; q++) {
            float2 f = __half22float2(hp[q]);
            acc[2 * q]     += a * f.x;
            acc[2 * q + 1] += a * f.y;
        }
    }
    int base = (u * NSLOT1 + part * 4 + js) * 128 + (b * 8 + c8) * 2;
    g_part[base]     = make_float4(acc[0], acc[1], acc[2], acc[3]);
    g_part[base + 1] = make_float4(acc[4], acc[5], acc[6], acc[7]);
}

// ---------------- combine out1 partials -> fp16 out1 ----------------
__global__ void k_combine1() {
    int idx = blockIdx.x * blockDim.x + threadIdx.x;    // NU*64
    if (idx >= NU * 64) return;
    int u = idx >> 6, b = (idx >> 3) & 7, c8 = idx & 7;
    float r[8] = {};
    #pragma unroll
    for (int s = 0; s < NSLOT1; s++) {
        int base = (u * NSLOT1 + s) * 128 + (b * 8 + c8) * 2;
        float4 t0 = g_part[base];
        float4 t1 = g_part[base + 1];
        r[0] += t0.x; r[1] += t0.y; r[2] += t0.z; r[3] += t0.w;
        r[4] += t1.x; r[5] += t1.y; r[6] += t1.z; r[7] += t1.w;
    }
    float bn = g_bn[u];
    H8 h;
    h.a = __floats2half2_rn(r[0] * bn, r[1] * bn);
    h.b = __floats2half2_rn(r[2] * bn, r[3] * bn);
    h.c = __floats2half2_rn(r[4] * bn, r[5] * bn);
    h.d = __floats2half2_rn(r[6] * bn, r[7] * bn);
    g_out1h[(u * 8 + b) * 8 + c8] = *(uint4*)&h;
}

// ---------------- stage 2: flat, thread per (n,b,c8), fp16 out1 ----------------
__global__ void k_out2(float* __restrict__ out) {
    int idx = blockIdx.x * blockDim.x + threadIdx.x;    // NNODE*64
    int n  = idx >> 6;
    int b  = (idx >> 3) & 7;
    int c8 = idx & 7;
    if (n >= NNODE) return;
    int s = g_rowstart[n], e2 = g_rowstart[n + 1];
    float acc[8] = {};
    for (int j = s; j < e2; j++) {
        int u = g_uperm[j];
        float a = g_alpha_p[j * NBAT + b];
        uint4 hv = g_out1h[(u * 8 + b) * 8 + c8];
        __half2* hp = (__half2*)&hv;
        #pragma unroll
        for (int q = 0; q < 4; q++) {
            float2 f = __half22float2(hp[q]);
            acc[2 * q]     += a * f.x;
            acc[2 * q + 1] += a * f.y;
        }
    }
    float D = (float)(e2 - s);
    float4* o4 = (float4*)out + ((size_t)b * NNODE + n) * 16 + c8 * 2;
    o4[0] = make_float4(acc[0] * D, acc[1] * D, acc[2] * D, acc[3] * D);
    o4[1] = make_float4(acc[4] * D, acc[5] * D, acc[6] * D, acc[7] * D);
}

extern "C" void kernel_launch(void* const* d_in, const int* in_sizes, int n_in,
                              void* d_out, int out_size) {
    const float* x   = (const float*)d_in[0];
    const float* Wq  = (const float*)d_in[1];
    const float* bq  = (const float*)d_in[2];
    const float* Wk  = (const float*)d_in[3];
    const float* bk  = (const float*)d_in[4];
    const float* Wv  = (const float*)d_in[5];
    const float* bv  = (const float*)d_in[6];
    const float* att = (const float*)d_in[7];
    const float* adj = (const float*)d_in[8];
    const int*   hi  = (const int*)d_in[9];
    float* out = (float*)d_out;

    static cudaStream_t s2 = nullptr;
    static cudaEvent_t ev0 = nullptr, ev2 = nullptr;
    if (s2 == nullptr) {
        cudaStreamCreateWithFlags(&s2, cudaStreamNonBlocking);
        cudaEventCreateWithFlags(&ev0, cudaEventDisableTiming);
        cudaEventCreateWithFlags(&ev2, cudaEventDisableTiming);
        size_t attn_smem = (size_t)(64 * 512 + 64 * 32 + 512) * sizeof(float);
        cudaFuncSetAttribute(k_attn, cudaFuncAttributeMaxDynamicSharedMemorySize,
                             (int)attn_smem);
    }

    // 0: init
    k_init<<<NSB + 1, 256>>>(hi, att, Wv, bv);
    cudaEventRecord(ev0, 0);
    cudaStreamWaitEvent(s2, ev0, 0);

    // side chain:    1, 2
    k_hist<<<NE / 256, 256, 0, s2>>>(hi);
    k_scan<<<NSB, SCAN_BS, 0, s2>>>();

    // 3 = ncu capture slot -> the split gather
    k_gather<<<NU * NPART, 256>>>(x, hi);

    // 4 (side): scatter + s_i + fp16 x copy
    k_scatsi<<<SCAT_BLOCKS + SI_BLOCKS, 256, 0, s2>>>(hi, x, att);
    cudaEventRecord(ev2, s2);

    // main chain
    k_project<<<NU, 256>>>(hi, Wq, bq, Wk, bk);                  // 5
    size_t attn_smem = (size_t)(64 * 512 + 64 * 32 + 512) * sizeof(float);
    k_attn<<<dim3(16, 8), 256, attn_smem>>>(adj);                // 6

    cudaStreamWaitEvent(0, ev2, 0);
    k_nodealpha<<<(NNODE * NBAT + 255) / 256, 256>>>();          // 7
    k_gather1<<<NU * NPART, 256>>>(hi);                          // 8
    k_combine1<<<(NU * 64 + 255) / 256, 256>>>();                // 9
    k_out2<<<(NNODE * 64 + 255) / 256, 256>>>(out);              // 10
}

// round 16
// speedup vs baseline: 1.1356x; 1.1356x over previous
#include <cuda_runtime.h>
#include <cuda_fp16.h>

#define NNODE 20000
#define NU    512
#define NE    81920
#define NBAT  8
#define NC    64
#define SEG   (NE / NU)        // 160 expected incidences per hyperedge
#define SCAN_BS 256
#define NSB   ((NNODE + SCAN_BS - 1) / SCAN_BS)   // 79
#define NPART 4                // gather blocks per hyperedge
#define NSLOT (NPART * 2)      // partial slots per hyperedge

// ---------------- device scratch ----------------
__device__ int   g_idx64;
__device__ int   g_uniform;
__device__ int   g_deg[NNODE];
__device__ int   g_rowstart[NNODE + 1];
__device__ int   g_cursor[NNODE];
__device__ int   g_bsum[NSB];
__device__ int   g_boff[NSB];
__device__ unsigned g_scan_ctr;
__device__ int   g_scan_flag;
__device__ int   g_perm[NE];
__device__ int   g_uperm[NE];
__device__ float g_si[NNODE * NBAT];
__device__ float g_sj[NU * NBAT];
__device__ float g_qt[NBAT * NC * NU];        // [b][c][u]
__device__ float g_kt[NBAT * NC * NU];        // [b][c][u]
__device__ float g_vj[NBAT * NU];
__device__ float g_wv[NC];
__device__ float g_cv;
__device__ float g_bn[NU];
__device__ float g_alpha_e[NE * NBAT];        // normalized alpha, original order
__device__ float g_alpha_p[NE * NBAT];        // normalized alpha, node-CSR order
__device__ uint4 g_out1h[NU * NBAT * 8];      // fp16 out1: [u][b][8x uint4 = 64 half]
__device__ float4 g_part[NU * NSLOT * 128];   // 8 partial slots per u

struct H8 { __half2 a, b, c, d; };

__device__ __forceinline__ int nodeAt(const int* hi, int e, int is64) {
    return is64 ? hi[2 * e] : hi[e];
}
__device__ __forceinline__ int edgeAt(const int* hi, int e, int is64) {
    return is64 ? hi[2 * (NE + e)] : hi[NE + e];
}
__device__ __forceinline__ int edgeLB(const int* hi, int target, int is64) {
    int lo = 0, hi_ = NE;
    while (lo < hi_) {
        int mid = (lo + hi_) >> 1;
        if (edgeAt(hi, mid, is64) < target) lo = mid + 1; else hi_ = mid;
    }
    return lo;
}

// ---------------- init: zero deg + detect dtype + uniformity + weff ----------------
__global__ void k_init(const int* __restrict__ hi, const float* __restrict__ att,
                       const float* __restrict__ Wv, const float* __restrict__ bv) {
    int blk = blockIdx.x;
    if (blk < NSB) {
        int i = blk * 256 + threadIdx.x;
        if (i < NNODE) g_deg[i] = 0;
        return;
    }
    __shared__ int s_is64;
    __shared__ int s_ok;
    int t = threadIdx.x;
    if (t == 0) {
        int odd_or = 0;
        for (int i = 0; i < 64; i++) odd_or |= hi[2 * i + 1];
        int is64 = (odd_or == 0) ? 1 : 0;
        g_idx64 = is64;
        s_is64 = is64;
        s_ok = 1;
        g_scan_ctr = 0;
        g_scan_flag = 0;
    }
    if (t < NC) {
        float w = 0.f;
        for (int c = 0; c < NC; c++) w += Wv[c * NC + t] * att[NC + c];
        g_wv[t] = w;
        if (t == 0) {
            float cv = 0.f;
            for (int c = 0; c < NC; c++) cv += bv[c] * att[NC + c];
            g_cv = cv;
        }
    }
    __syncthreads();
    int is64 = s_is64;
    int ok = 1;
    for (int u = t; u < NU; u += 256) {
        if (edgeAt(hi, u * SEG, is64) != u) ok = 0;
        if (edgeAt(hi, u * SEG + SEG - 1, is64) != u) ok = 0;
    }
    if (!ok) atomicAnd(&s_ok, 0);
    __syncthreads();
    if (t == 0) g_uniform = s_ok;
}

__global__ void k_hist(const int* __restrict__ hi) {
    int i = blockIdx.x * blockDim.x + threadIdx.x;
    if (i >= NE) return;
    atomicAdd(&g_deg[nodeAt(hi, i, g_idx64)], 1);
}

// ---------------- single-kernel scan ----------------
__global__ void k_scan() {
    __shared__ int wsum[8];
    __shared__ int isLast;
    int tid = threadIdx.x, lane = tid & 31, w = tid >> 5;
    int i = blockIdx.x * SCAN_BS + tid;
    int v = (i < NNODE) ? g_deg[i] : 0;
    int xv = v;
    #pragma unroll
    for (int o = 1; o < 32; o <<= 1) {
        int y = __shfl_up_sync(0xffffffffu, xv, o);
        if (lane >= o) xv += y;
    }
    if (lane == 31) wsum[w] = xv;
    __syncthreads();
    if (w == 0) {
        int t = (lane < 8) ? wsum[lane] : 0;
        #pragma unroll
        for (int o = 1; o < 8; o <<= 1) {
            int y = __shfl_up_sync(0xffffffffu, t, o);
            if (lane >= o) t += y;
        }
        if (lane < 8) wsum[lane] = t;
    }
    __syncthreads();
    int woff = (w == 0) ? 0 : wsum[w - 1];
    int local_excl = woff + xv - v;
    if (tid == 0) g_bsum[blockIdx.x] = wsum[7];
    __threadfence();
    if (tid == 0) {
        unsigned d = atomicAdd(&g_scan_ctr, 1u);
        isLast = (d == NSB - 1) ? 1 : 0;
    }
    __syncthreads();
    if (isLast) {
        int v2 = (tid < NSB) ? g_bsum[tid] : 0;
        int xv2 = v2;
        #pragma unroll
        for (int o = 1; o < 32; o <<= 1) {
            int y = __shfl_up_sync(0xffffffffu, xv2, o);
            if (lane >= o) xv2 += y;
        }
        __syncthreads();
        if (lane == 31) wsum[w] = xv2;
        __syncthreads();
        if (w == 0) {
            int t = (lane < 8) ? wsum[lane] : 0;
            #pragma unroll
            for (int o = 1; o < 8; o <<= 1) {
                int y = __shfl_up_sync(0xffffffffu, t, o);
                if (lane >= o) t += y;
            }
            if (lane < 8) wsum[lane] = t;
        }
        __syncthreads();
        int woff2 = (w == 0) ? 0 : wsum[w - 1];
        if (tid < NSB) g_boff[tid] = woff2 + xv2 - v2;
        __threadfence();
        __syncthreads();
        if (tid == 0) atomicExch(&g_scan_flag, 1);
    } else {
        if (tid == 0) {
            while (atomicAdd(&g_scan_flag, 0) == 0) __nanosleep(40);
        }
        __syncthreads();
    }
    int boff = __ldcg(&g_boff[blockIdx.x]);
    if (i < NNODE) {
        int r = local_excl + boff;
        g_rowstart[i] = r;
        g_cursor[i] = r;
    }
    if (i == 0) g_rowstart[NNODE] = NE;
}

// ---------------- fused scatter + s_i ----------------
#define SCAT_BLOCKS (NE / 256)                          // 320
#define SI_BLOCKS   ((NNODE * NBAT + 255) / 256)        // 625
__global__ void k_scatsi(const int* __restrict__ hi, const float* __restrict__ x,
                         const float* __restrict__ att) {
    int blk = blockIdx.x;
    if (blk < SCAT_BLOCKS) {
        int e = blk * 256 + threadIdx.x;
        int is64 = g_idx64;
        int n = nodeAt(hi, e, is64);
        int pos = atomicAdd(&g_cursor[n], 1);
        g_perm[pos] = e;
        g_uperm[pos] = edgeAt(hi, e, is64);
        return;
    }
    int idx = (blk - SCAT_BLOCKS) * 256 + threadIdx.x;
    if (idx >= NNODE * NBAT) return;
    int b = idx / NNODE;
    int n = idx - b * NNODE;
    const float4* x4 = (const float4*)x + (size_t)idx * 16;
    const float4* a4 = (const float4*)att;
    float v = 0.f;
    #pragma unroll
    for (int i = 0; i < 16; i++) {
        float4 xv = x4[i], av = a4[i];
        v += xv.x * av.x + xv.y * av.y + xv.z * av.z + xv.w * av.w;
    }
    g_si[n * NBAT + b] = v;
}

// ---------------- agg gather: 4 blocks per u, high occupancy ----------------
__global__ void __launch_bounds__(256, 8) k_gather(const float* __restrict__ x,
                                                   const int* __restrict__ hi) {
    int blk = blockIdx.x;                 // NU*4 = 2048
    int u = blk >> 2, part = blk & 3;
    int is64 = g_idx64;
    __shared__ int sb[2];
    if (g_uniform) {
        if (threadIdx.x < 2) sb[threadIdx.x] = (u + threadIdx.x) * SEG;
    } else {
        if (threadIdx.x < 2) sb[threadIdx.x] = edgeLB(hi, u + threadIdx.x, is64);
    }
    __syncthreads();
    int start = sb[0], end = sb[1];
    int len = end - start;
    int chunk = (len + NPART - 1) / NPART;
    int lo = start + part * chunk;
    int hi_ = min(lo + chunk, end);

    int js = threadIdx.x >> 7;            // 2 j-slots
    int b  = (threadIdx.x >> 4) & 7;
    int c4 = threadIdx.x & 15;
    const float4* x4 = (const float4*)x;
    float4 acc = make_float4(0.f, 0.f, 0.f, 0.f);
    #pragma unroll 4
    for (int j = lo + js; j < hi_; j += 2) {
        int n = nodeAt(hi, j, is64);
        float4 xv = x4[((size_t)b * NNODE + n) * 16 + c4];
        acc.x += xv.x; acc.y += xv.y; acc.z += xv.z; acc.w += xv.w;
    }
    g_part[(u * NSLOT + part * 2 + js) * 128 + b * 16 + c4] = acc;
}

// ---------------- project: reduce partials -> agg ; q,k,vj ----------------
__global__ void __launch_bounds__(256, 4) k_project(
        const int* __restrict__ hi,
        const float* __restrict__ Wq, const float* __restrict__ bq,
        const float* __restrict__ Wk, const float* __restrict__ bk) {
    __shared__ float wq_s[64 * 65];
    __shared__ float wk_s[64 * 65];
    __shared__ float agg_s[8][65];
    __shared__ float wv_s[64];
    int u = blockIdx.x;
    int tid = threadIdx.x;

    for (int i = tid; i < 4096; i += 256) {
        int c = i >> 6, k = i & 63;
        wq_s[c * 65 + k] = Wq[i];
        wk_s[c * 65 + k] = Wk[i];
    }
    if (tid < 64) wv_s[tid] = g_wv[tid];
    if (tid == 0) {
        int len = g_uniform ? SEG : (edgeLB(hi, u + 1, g_idx64) - edgeLB(hi, u, g_idx64));
        g_bn[u] = (len > 0) ? 1.0f / (float)len : 0.0f;
    }
    if (tid < 128) {
        float4 r = make_float4(0.f, 0.f, 0.f, 0.f);
        #pragma unroll
        for (int s = 0; s < NSLOT; s++) {
            float4 t = g_part[(u * NSLOT + s) * 128 + tid];
            r.x += t.x; r.y += t.y; r.z += t.z; r.w += t.w;
        }
        int bb = tid >> 4, cc = (tid & 15) * 4;
        agg_s[bb][cc + 0] = r.x;
        agg_s[bb][cc + 1] = r.y;
        agg_s[bb][cc + 2] = r.z;
        agg_s[bb][cc + 3] = r.w;
    }
    __syncthreads();

    #pragma unroll
    for (int p = 0; p < 2; p++) {
        int pp = tid + p * 256;
        int c = pp & 63, b2 = pp >> 6;
        float qa = bq[c], ka = bk[c];
        #pragma unroll 8
        for (int k = 0; k < 64; k++) {
            float a = agg_s[b2][k];
            qa += a * wq_s[c * 65 + k];
            ka += a * wk_s[c * 65 + k];
        }
        g_qt[(b2 * 64 + c) * NU + u] = qa;
        g_kt[(b2 * 64 + c) * NU + u] = ka;
    }

    int w = tid >> 5, lane = tid & 31;
    float v = agg_s[w][lane] * wv_s[lane] + agg_s[w][lane + 32] * wv_s[lane + 32];
    #pragma unroll
    for (int o = 16; o; o >>= 1) v += __shfl_down_sync(0xffffffffu, v, o);
    if (lane == 0) g_vj[w * NU + u] = v + g_cv;
}

// ---------------- masked attention + register softmax -> s_j ----------------
__global__ void __launch_bounds__(256, 1) k_attn(const float* __restrict__ adj) {
    extern __shared__ float sm[];
    float* k_s  = sm;
    float* q_s  = k_s + 64 * 512;
    float* vj_s = q_s + 64 * 32;
    __shared__ float redm[8][8];
    __shared__ float reds[8][8];
    __shared__ float redd[8][8];

    int b  = blockIdx.y;
    int u0 = blockIdx.x * 32;
    int tid = threadIdx.x;

    const float4* ksrc = (const float4*)(g_kt) + (size_t)b * (64 * NU / 4);
    float4* kdst = (float4*)k_s;
    for (int i = tid; i < 64 * NU / 4; i += 256) kdst[i] = ksrc[i];
    for (int i = tid; i < 64 * 32; i += 256) {
        int c = i >> 5, u = i & 31;
        q_s[c * 32 + u] = g_qt[(b * 64 + c) * NU + u0 + u];
    }
    for (int i = tid; i < 512; i += 256) vj_s[i] = g_vj[b * NU + i];
    __syncthreads();

    int g  = tid >> 6;
    int ug = g * 8;
    int vg = (tid & 63) * 8;
    float acc[8][8] = {};
    const float4* k4 = (const float4*)k_s;
    const float4* q4 = (const float4*)q_s;
    int kv_i = vg >> 2, qu_i = ug >> 2;
    #pragma unroll 4
    for (int kk = 0; kk < 64; kk++) {
        float4 kv0 = k4[kk * 128 + kv_i];
        float4 kv1 = k4[kk * 128 + kv_i + 1];
        float4 qv0 = q4[kk * 8 + qu_i];
        float4 qv1 = q4[kk * 8 + qu_i + 1];
        float qa[8] = {qv0.x, qv0.y, qv0.z, qv0.w, qv1.x, qv1.y, qv1.z, qv1.w};
        float kb[8] = {kv0.x, kv0.y, kv0.z, kv0.w, kv1.x, kv1.y, kv1.z, kv1.w};
        #pragma unroll
        for (int i = 0; i < 8; i++)
            #pragma unroll
            for (int j = 0; j < 8; j++)
                acc[i][j] += qa[i] * kb[j];
    }
    float rm[8];
    #pragma unroll
    for (int i = 0; i < 8; i++) {
        int u = ug + i;
        const float4* arow = (const float4*)(adj + (size_t)(u0 + u) * NU + vg);
        float4 a0 = arow[0], a1 = arow[1];
        acc[i][0] = acc[i][0] * 0.125f - (1.f - a0.x) * 500.f;
        acc[i][1] = acc[i][1] * 0.125f - (1.f - a0.y) * 500.f;
        acc[i][2] = acc[i][2] * 0.125f - (1.f - a0.z) * 500.f;
        acc[i][3] = acc[i][3] * 0.125f - (1.f - a0.w) * 500.f;
        acc[i][4] = acc[i][4] * 0.125f - (1.f - a1.x) * 500.f;
        acc[i][5] = acc[i][5] * 0.125f - (1.f - a1.y) * 500.f;
        acc[i][6] = acc[i][6] * 0.125f - (1.f - a1.z) * 500.f;
        acc[i][7] = acc[i][7] * 0.125f - (1.f - a1.w) * 500.f;
        float m = acc[i][0];
        #pragma unroll
        for (int j = 1; j < 8; j++) m = fmaxf(m, acc[i][j]);
        rm[i] = m;
    }
    int w = tid >> 5, lane = tid & 31;
    #pragma unroll
    for (int i = 0; i < 8; i++) {
        float m = rm[i];
        #pragma unroll
        for (int o = 16; o; o >>= 1) m = fmaxf(m, __shfl_xor_sync(0xffffffffu, m, o));
        if (lane == 0) redm[w][i] = m;
    }
    __syncthreads();
    #pragma unroll
    for (int i = 0; i < 8; i++) rm[i] = fmaxf(redm[g * 2][i], redm[g * 2 + 1][i]);

    float vjv[8];
    {
        const float4* v4 = (const float4*)(vj_s + vg);
        float4 v0 = v4[0], v1 = v4[1];
        vjv[0] = v0.x; vjv[1] = v0.y; vjv[2] = v0.z; vjv[3] = v0.w;
        vjv[4] = v1.x; vjv[5] = v1.y; vjv[6] = v1.z; vjv[7] = v1.w;
    }
    #pragma unroll
    for (int i = 0; i < 8; i++) {
        float s = 0.f, d = 0.f;
        #pragma unroll
        for (int j = 0; j < 8; j++) {
            float e = __expf(acc[i][j] - rm[i]);
            s += e;
            d += e * vjv[j];
        }
        #pragma unroll
        for (int o = 16; o; o >>= 1) {
            s += __shfl_xor_sync(0xffffffffu, s, o);
            d += __shfl_xor_sync(0xffffffffu, d, o);
        }
        if (lane == 0) { reds[w][i] = s; redd[w][i] = d; }
    }
    __syncthreads();
    if ((tid & 63) < 8) {
        int i = tid & 63;
        float s = reds[g * 2][i] + reds[g * 2 + 1][i];
        float d = redd[g * 2][i] + redd[g * 2 + 1][i];
        g_sj[(u0 + ug + i) * NBAT + b] = d / s;
    }
}

// ---------------- 2-pass node softmax (no max pass; |a| is O(1)) ----------------
__global__ void k_nodealpha() {
    int idx = blockIdx.x * blockDim.x + threadIdx.x;
    if (idx >= NNODE * NBAT) return;
    int n = idx >> 3, b = idx & 7;
    int s = g_rowstart[n], e2 = g_rowstart[n + 1];
    if (s == e2) return;
    float si = g_si[n * NBAT + b];
    float sum = 0.f;
    for (int j = s; j < e2; j++) {
        int u = g_uperm[j];
        float a = si + g_sj[u * NBAT + b];
        a = (a > 0.f) ? a : 0.2f * a;
        float ex = __expf(a);
        g_alpha_p[j * NBAT + b] = ex;
        sum += ex;
    }
    float inv = 1.0f / (sum + 1e-16f);
    for (int j = s; j < e2; j++) {
        float v = g_alpha_p[j * NBAT + b] * inv;
        g_alpha_p[j * NBAT + b] = v;
        g_alpha_e[g_perm[j] * NBAT + b] = v;
    }
}

// ---------------- out1 gather: 4 blocks per u (R14 form, fp32 x) ----------------
__global__ void __launch_bounds__(256, 8) k_gather1(const float* __restrict__ x,
                                                    const int* __restrict__ hi) {
    int blk = blockIdx.x;                 // NU*4
    int u = blk >> 2, part = blk & 3;
    int is64 = g_idx64;
    __shared__ int sb[2];
    if (g_uniform) {
        if (threadIdx.x < 2) sb[threadIdx.x] = (u + threadIdx.x) * SEG;
    } else {
        if (threadIdx.x < 2) sb[threadIdx.x] = edgeLB(hi, u + threadIdx.x, is64);
    }
    __syncthreads();
    int start = sb[0], end = sb[1];
    int len = end - start;
    int chunk = (len + NPART - 1) / NPART;
    int lo = start + part * chunk;
    int hi_ = min(lo + chunk, end);

    int js = threadIdx.x >> 7;
    int b  = (threadIdx.x >> 4) & 7;
    int c4 = threadIdx.x & 15;
    const float4* x4 = (const float4*)x;
    float4 acc = make_float4(0.f, 0.f, 0.f, 0.f);
    #pragma unroll 4
    for (int j = lo + js; j < hi_; j += 2) {
        int n = nodeAt(hi, j, is64);
        float a = g_alpha_e[j * NBAT + b];
        float4 xv = x4[((size_t)b * NNODE + n) * 16 + c4];
        acc.x += a * xv.x; acc.y += a * xv.y; acc.z += a * xv.z; acc.w += a * xv.w;
    }
    g_part[(u * NSLOT + part * 2 + js) * 128 + b * 16 + c4] = acc;
}

// ---------------- combine out1 partials -> fp16 out1 ----------------
__global__ void k_combine1() {
    int idx = blockIdx.x * blockDim.x + threadIdx.x;    // NU*64
    if (idx >= NU * 64) return;
    int u = idx >> 6;
    int slot2 = (idx & 63) * 2;     // 2 consecutive float4 slots = 8 channels
    float r[8] = {};
    #pragma unroll
    for (int s = 0; s < NSLOT; s++) {
        float4 t0 = g_part[(u * NSLOT + s) * 128 + slot2];
        float4 t1 = g_part[(u * NSLOT + s) * 128 + slot2 + 1];
        r[0] += t0.x; r[1] += t0.y; r[2] += t0.z; r[3] += t0.w;
        r[4] += t1.x; r[5] += t1.y; r[6] += t1.z; r[7] += t1.w;
    }
    float bn = g_bn[u];
    H8 h;
    h.a = __floats2half2_rn(r[0] * bn, r[1] * bn);
    h.b = __floats2half2_rn(r[2] * bn, r[3] * bn);
    h.c = __floats2half2_rn(r[4] * bn, r[5] * bn);
    h.d = __floats2half2_rn(r[6] * bn, r[7] * bn);
    // slot2 = (b*16 + c4); c8 = c4/2 where c4 even. idx&63 = b*8 + c8
    g_out1h[(size_t)u * 64 + (idx & 63)] = *(uint4*)&h;
}

// ---------------- stage 2: flat, thread per (n,b,c8), fp16 out1 ----------------
__global__ void k_out2(float* __restrict__ out) {
    int idx = blockIdx.x * blockDim.x + threadIdx.x;    // NNODE*64
    int n  = idx >> 6;
    int b  = (idx >> 3) & 7;
    int c8 = idx & 7;
    if (n >= NNODE) return;
    int s = g_rowstart[n], e2 = g_rowstart[n + 1];
    float acc[8] = {};
    for (int j = s; j < e2; j++) {
        int u = g_uperm[j];
        float a = g_alpha_p[j * NBAT + b];
        uint4 hv = g_out1h[(size_t)u * 64 + b * 8 + c8];
        __half2* hp = (__half2*)&hv;
        #pragma unroll
        for (int q = 0; q < 4; q++) {
            float2 f = __half22float2(hp[q]);
            acc[2 * q]     += a * f.x;
            acc[2 * q + 1] += a * f.y;
        }
    }
    float D = (float)(e2 - s);
    float4* o4 = (float4*)out + ((size_t)b * NNODE + n) * 16 + c8 * 2;
    o4[0] = make_float4(acc[0] * D, acc[1] * D, acc[2] * D, acc[3] * D);
    o4[1] = make_float4(acc[4] * D, acc[5] * D, acc[6] * D, acc[7] * D);
}

extern "C" void kernel_launch(void* const* d_in, const int* in_sizes, int n_in,
                              void* d_out, int out_size) {
    const float* x   = (const float*)d_in[0];
    const float* Wq  = (const float*)d_in[1];
    const float* bq  = (const float*)d_in[2];
    const float* Wk  = (const float*)d_in[3];
    const float* bk  = (const float*)d_in[4];
    const float* Wv  = (const float*)d_in[5];
    const float* bv  = (const float*)d_in[6];
    const float* att = (const float*)d_in[7];
    const float* adj = (const float*)d_in[8];
    const int*   hi  = (const int*)d_in[9];
    float* out = (float*)d_out;

    static cudaStream_t s2 = nullptr;
    static cudaEvent_t ev0 = nullptr, ev2 = nullptr;
    if (s2 == nullptr) {
        cudaStreamCreateWithFlags(&s2, cudaStreamNonBlocking);
        cudaEventCreateWithFlags(&ev0, cudaEventDisableTiming);
        cudaEventCreateWithFlags(&ev2, cudaEventDisableTiming);
        size_t attn_smem = (size_t)(64 * 512 + 64 * 32 + 512) * sizeof(float);
        cudaFuncSetAttribute(k_attn, cudaFuncAttributeMaxDynamicSharedMemorySize,
                             (int)attn_smem);
    }

    // 0: init
    k_init<<<NSB + 1, 256>>>(hi, att, Wv, bv);
    cudaEventRecord(ev0, 0);
    cudaStreamWaitEvent(s2, ev0, 0);

    // side chain:    1, 2
    k_hist<<<NE / 256, 256, 0, s2>>>(hi);
    k_scan<<<NSB, SCAN_BS, 0, s2>>>();

    // 3 = ncu capture slot -> the split gather
    k_gather<<<NU * NPART, 256>>>(x, hi);

    // 4 (side)
    k_scatsi<<<SCAT_BLOCKS + SI_BLOCKS, 256, 0, s2>>>(hi, x, att);
    cudaEventRecord(ev2, s2);

    // main chain
    k_project<<<NU, 256>>>(hi, Wq, bq, Wk, bk);                  // 5
    size_t attn_smem = (size_t)(64 * 512 + 64 * 32 + 512) * sizeof(float);
    k_attn<<<dim3(16, 8), 256, attn_smem>>>(adj);                // 6

    cudaStreamWaitEvent(0, ev2, 0);
    k_nodealpha<<<(NNODE * NBAT + 255) / 256, 256>>>();          // 7
    k_gather1<<<NU * NPART, 256>>>(x, hi);                       // 8
    k_combine1<<<(NU * 64 + 255) / 256, 256>>>();                // 9
    k_out2<<<(NNODE * 64 + 255) / 256, 256>>>(out);              // 10
}